// round 6
// baseline (speedup 1.0000x reference)
#include <cuda_runtime.h>
#include <math.h>
#include <stdint.h>

#define NN 100000
#define EE 300000
#define DD 256
#define FDIM 512
#define LL 5
#define GG 4000
#define NUM_BOND_C 2
#define BN_EPS 1e-5f

// ---------------- scratch (device globals: no allocation allowed) ----------------
__device__ float g_h[(size_t)NN * DD];
__device__ float g_agg[(size_t)NN * DD];
__device__ float g_tmp[(size_t)NN * FDIM];
__device__ float g_stat[2 * FDIM];
__device__ float g_ab[2 * DD];
__device__ float g_ssum[(size_t)GG * FDIM];
__device__ float g_cnt[GG];
__device__ float g_gfeat[(size_t)GG * FDIM];
__device__ float g_hid[(size_t)GG * (FDIM / 2)];
// permuted + tf32-split weights (same [K,N] shape, columns permuted per 128-tile):
// w1[l] @ l*131072 | w2[l] @ 655360+l*131072 | feat @ 1310720 | head @ 1441792
#define WT_TOTAL 1572864
__device__ float g_w_hi[WT_TOTAL];
__device__ float g_w_lo[WT_TOTAL];

__device__ __forceinline__ float softplus_f(float x) {
    return fmaxf(x, 0.0f) + log1pf(expf(-fabsf(x)));
}

__device__ __forceinline__ void red_add_v4(float* p, float x, float y, float z, float w) {
    asm volatile("red.global.add.v4.f32 [%0], {%1,%2,%3,%4};"
                 :: "l"(p), "f"(x), "f"(y), "f"(z), "f"(w) : "memory");
}
__device__ __forceinline__ void red_add_f32(float* p, float v) {
    asm volatile("red.global.add.f32 [%0], %1;" :: "l"(p), "f"(v) : "memory");
}

// ---------------- tf32 helpers ----------------
__device__ __forceinline__ void split_tf32(float x, uint32_t& hi, uint32_t& lo) {
    uint32_t h = __float_as_uint(x) & 0xffffe000u;
    hi = h;
    lo = __float_as_uint(x - __uint_as_float(h));
}

__device__ __forceinline__ void mma8(float* c, const uint32_t* a, uint32_t b0, uint32_t b1) {
    asm volatile(
        "mma.sync.aligned.m16n8k8.row.col.f32.tf32.tf32.f32 "
        "{%0,%1,%2,%3},{%4,%5,%6,%7},{%8,%9},{%0,%1,%2,%3};"
        : "+f"(c[0]), "+f"(c[1]), "+f"(c[2]), "+f"(c[3])
        : "r"(a[0]), "r"(a[1]), "r"(a[2]), "r"(a[3]), "r"(b0), "r"(b1));
}

__device__ __forceinline__ void cpa16(void* dst, const void* src, int srcBytes) {
    uint32_t d = (uint32_t)__cvta_generic_to_shared(dst);
    asm volatile("cp.async.cg.shared.global [%0], [%1], 16, %2;"
                 :: "r"(d), "l"(src), "r"(srcBytes) : "memory");
}
__device__ __forceinline__ void cpa16f(void* dst, const void* src) {
    uint32_t d = (uint32_t)__cvta_generic_to_shared(dst);
    asm volatile("cp.async.cg.shared.global [%0], [%1], 16;"
                 :: "r"(d), "l"(src) : "memory");
}
__device__ __forceinline__ void cp_commit() {
    asm volatile("cp.async.commit_group;" ::: "memory");
}
__device__ __forceinline__ void cp_wait0() {
    asm volatile("cp.async.wait_group 0;" ::: "memory");
}

// ---------------- weight prep: tf32 split + fragment permutation ----------------
// source col n (within 128-tile): n = half*64 + nt*8 + g
// dest col p:                     p = g*16 + half*8 + nt
__global__ void split_perm_kernel(const float* __restrict__ W, float* __restrict__ hi,
                                  float* __restrict__ lo, int total) {
    int idx = blockIdx.x * blockDim.x + threadIdx.x;
    if (idx >= total) return;
    float v = W[idx];
    uint32_t h = __float_as_uint(v) & 0xffffe000u;
    int n128 = idx & 127;
    int g = n128 & 7;
    int nt = (n128 >> 3) & 7;
    int half = n128 >> 6;
    int p = g * 16 + half * 8 + nt;
    int dst = (idx & ~127) | p;
    hi[dst] = __uint_as_float(h);
    lo[dst] = v - __uint_as_float(h);
}

// ---------------- init: h = x_emb1[atomics] + pos @ x_emb2_w + b ----------------
__global__ void init_h_kernel(const int* __restrict__ atomics,
                              const float* __restrict__ pos,
                              const float* __restrict__ emb1,
                              const float* __restrict__ w2,
                              const float* __restrict__ b2,
                              float* __restrict__ h) {
    size_t idx = (size_t)blockIdx.x * blockDim.x + threadIdx.x;
    if (idx >= (size_t)NN * DD) return;
    int i = (int)(idx / DD);
    int d = (int)(idx & (DD - 1));
    float p0 = pos[i * 3 + 0], p1 = pos[i * 3 + 1], p2 = pos[i * 3 + 2];
    float v = emb1[(size_t)atomics[i] * DD + d];
    v += p0 * w2[d] + p1 * w2[DD + d] + p2 * w2[2 * DD + d] + b2[d];
    h[idx] = v;
}

__global__ void agg_init_kernel(const float* __restrict__ h,
                                const float* __restrict__ emb_self,
                                float* __restrict__ agg) {
    size_t idx = (size_t)blockIdx.x * blockDim.x + threadIdx.x;
    if (idx >= (size_t)NN * DD / 4) return;
    int d4 = (int)(idx & (DD / 4 - 1)) * 4;
    float4 hv = *((const float4*)h + idx);
    float4 ev = *(const float4*)(emb_self + d4);
    *((float4*)agg + idx) = make_float4(hv.x + ev.x, hv.y + ev.y, hv.z + ev.z, hv.w + ev.w);
}

__global__ void scatter_edges_kernel(const float* __restrict__ h,
                                     const int* __restrict__ edge_index,
                                     const int* __restrict__ edge_attr,
                                     const float* __restrict__ emb,
                                     float* __restrict__ agg) {
    int e = blockIdx.x * (blockDim.x >> 5) + (threadIdx.x >> 5);
    if (e >= EE) return;
    int lane = threadIdx.x & 31;
    int s = edge_index[e];
    int t = edge_index[EE + e];
    const float* hs = h + (size_t)s * DD;
    const float* eb = emb + (size_t)edge_attr[e] * DD;
    float* ag = agg + (size_t)t * DD;
#pragma unroll
    for (int half = 0; half < 2; half++) {
        int c = lane * 4 + half * 128;
        float4 hv = *(const float4*)(hs + c);
        float4 ev = *(const float4*)(eb + c);
        red_add_v4(ag + c, hv.x + ev.x, hv.y + ev.y, hv.z + ev.z, hv.w + ev.w);
    }
}

// ---------------- tf32x3 tensor-core GEMM (permuted pre-split B) ----------------
// C[M,Nc] = act(A[M,K] @ B[K,Nc] + bias); B hi/lo in permuted fragment layout.
// 128x128x16 block tile, 256 threads = 8 warps (4x2), warp tile 32x64,
// 2-stage cp.async double buffer (R3 schedule).
// smem floats: As[2][128][20] @0 | Bh[2][16][132] @5120 | Bl @9344; total 13568 fl.
#define SM_AS(s, m, k) smp[(s) * 2560 + (m) * 20 + (k)]
#define SM_BH(s, k, p) smp[5120 + (s) * 2112 + (k) * 132 + (p)]
#define SM_BL(s, k, p) smp[9344 + (s) * 2112 + (k) * 132 + (p)]
#define GEMM_SMEM_BYTES (13568 * 4)

__global__ __launch_bounds__(256, 2)
void gemm_tf32(const float* __restrict__ A, const float* __restrict__ Bhi,
               const float* __restrict__ Blo, const float* __restrict__ bias,
               float* __restrict__ C, int M, int K, int Nc, int act,
               float* __restrict__ stat) {
    extern __shared__ float smp[];

    const int tid = threadIdx.x;
    const int lane = tid & 31;
    const int w = tid >> 5;
    const int g = lane >> 2;
    const int t = lane & 3;
    const int warp_m = (w >> 1) * 32;
    const int warp_n = (w & 1) * 64;
    const int brow = blockIdx.y * 128;
    const int bcol = blockIdx.x * 128;
    const int pbase = g * 16 + (warp_n >> 6) * 8;  // permuted fragment base

    // fill mappings: chunks c = tid*2 + {0,1} over 512 16B-chunks
    const int ac0 = tid * 2;
    const int a_row0 = ac0 >> 2, a_k0 = (ac0 & 3) * 4;
    const int a_row1 = (ac0 + 1) >> 2, a_k1 = ((ac0 + 1) & 3) * 4;
    const bool a_ok0 = (brow + a_row0) < M;
    const bool a_ok1 = (brow + a_row1) < M;
    const float* Ag0 = A + (size_t)(a_ok0 ? brow + a_row0 : 0) * K + a_k0;
    const float* Ag1 = A + (size_t)(a_ok1 ? brow + a_row1 : 0) * K + a_k1;

    const int b_k0 = ac0 >> 5, b_p0 = (ac0 & 31) * 4;
    const int b_k1 = (ac0 + 1) >> 5, b_p1 = ((ac0 + 1) & 31) * 4;
    const float* Bh0 = Bhi + (size_t)b_k0 * Nc + bcol + b_p0;
    const float* Bh1 = Bhi + (size_t)b_k1 * Nc + bcol + b_p1;
    const float* Bl0 = Blo + (size_t)b_k0 * Nc + bcol + b_p0;
    const float* Bl1 = Blo + (size_t)b_k1 * Nc + bcol + b_p1;

    float acc[2][8][4];
#pragma unroll
    for (int mt = 0; mt < 2; mt++)
#pragma unroll
        for (int nt = 0; nt < 8; nt++)
#pragma unroll
            for (int q = 0; q < 4; q++) acc[mt][nt][q] = 0.0f;

    const int T = K >> 4;

#define PREFETCH(stage, buf)                                                  \
    do {                                                                      \
        const int ko_ = (stage) << 4;                                        \
        cpa16(&SM_AS(buf, a_row0, a_k0), Ag0 + ko_, a_ok0 ? 16 : 0);         \
        cpa16(&SM_AS(buf, a_row1, a_k1), Ag1 + ko_, a_ok1 ? 16 : 0);         \
        cpa16f(&SM_BH(buf, b_k0, b_p0), Bh0 + (size_t)ko_ * Nc);             \
        cpa16f(&SM_BH(buf, b_k1, b_p1), Bh1 + (size_t)ko_ * Nc);             \
        cpa16f(&SM_BL(buf, b_k0, b_p0), Bl0 + (size_t)ko_ * Nc);             \
        cpa16f(&SM_BL(buf, b_k1, b_p1), Bl1 + (size_t)ko_ * Nc);             \
    } while (0)

    PREFETCH(0, 0);
    cp_commit();

    for (int s = 0; s < T; s++) {
        const int buf = s & 1;
        cp_wait0();
        __syncthreads();
        if (s + 1 < T) PREFETCH(s + 1, buf ^ 1);
        cp_commit();

#pragma unroll
        for (int kk = 0; kk < 16; kk += 8) {
            uint32_t ah[2][4], al[2][4];
#pragma unroll
            for (int mt = 0; mt < 2; mt++) {
                const int mr = warp_m + mt * 16 + g;
                split_tf32(SM_AS(buf, mr, kk + t), ah[mt][0], al[mt][0]);
                split_tf32(SM_AS(buf, mr + 8, kk + t), ah[mt][1], al[mt][1]);
                split_tf32(SM_AS(buf, mr, kk + t + 4), ah[mt][2], al[mt][2]);
                split_tf32(SM_AS(buf, mr + 8, kk + t + 4), ah[mt][3], al[mt][3]);
            }
#pragma unroll
            for (int nt0 = 0; nt0 < 8; nt0 += 4) {
                float4 h0 = *(const float4*)&SM_BH(buf, kk + t, pbase + nt0);
                float4 h1 = *(const float4*)&SM_BH(buf, kk + t + 4, pbase + nt0);
                float4 l0 = *(const float4*)&SM_BL(buf, kk + t, pbase + nt0);
                float4 l1 = *(const float4*)&SM_BL(buf, kk + t + 4, pbase + nt0);
                const float h0a[4] = {h0.x, h0.y, h0.z, h0.w};
                const float h1a[4] = {h1.x, h1.y, h1.z, h1.w};
                const float l0a[4] = {l0.x, l0.y, l0.z, l0.w};
                const float l1a[4] = {l1.x, l1.y, l1.z, l1.w};
#pragma unroll
                for (int j = 0; j < 4; j++) {
                    const int nt = nt0 + j;
                    uint32_t bh0 = __float_as_uint(h0a[j]);
                    uint32_t bh1 = __float_as_uint(h1a[j]);
                    uint32_t bl0 = __float_as_uint(l0a[j]);
                    uint32_t bl1 = __float_as_uint(l1a[j]);
#pragma unroll
                    for (int mt = 0; mt < 2; mt++) {
                        mma8(acc[mt][nt], ah[mt], bh0, bh1);
                        mma8(acc[mt][nt], ah[mt], bl0, bl1);
                        mma8(acc[mt][nt], al[mt], bh0, bh1);
                    }
                }
            }
        }
    }

    // ---------------- epilogue ----------------
    const bool do_stats = (stat != nullptr);
    float csum[16], csq[16];
    if (do_stats) {
#pragma unroll
        for (int i = 0; i < 16; i++) { csum[i] = 0.f; csq[i] = 0.f; }
    }

#pragma unroll
    for (int mt = 0; mt < 2; mt++) {
        const int r0 = brow + warp_m + mt * 16 + g;
#pragma unroll
        for (int nt = 0; nt < 8; nt++) {
            const int col = bcol + warp_n + nt * 8 + t * 2;
            const float b0v = bias[col];
            const float b1v = bias[col + 1];
            float v0 = acc[mt][nt][0] + b0v;
            float v1 = acc[mt][nt][1] + b1v;
            float v2 = acc[mt][nt][2] + b0v;
            float v3 = acc[mt][nt][3] + b1v;
            if (act) {
                v0 = softplus_f(v0); v1 = softplus_f(v1);
                v2 = softplus_f(v2); v3 = softplus_f(v3);
            }
            if (r0 < M) {
                *(float2*)&C[(size_t)r0 * Nc + col] = make_float2(v0, v1);
                if (do_stats) {
                    csum[nt * 2] += v0; csq[nt * 2] += v0 * v0;
                    csum[nt * 2 + 1] += v1; csq[nt * 2 + 1] += v1 * v1;
                }
            }
            if (r0 + 8 < M) {
                *(float2*)&C[(size_t)(r0 + 8) * Nc + col] = make_float2(v2, v3);
                if (do_stats) {
                    csum[nt * 2] += v2; csq[nt * 2] += v2 * v2;
                    csum[nt * 2 + 1] += v3; csq[nt * 2 + 1] += v3 * v3;
                }
            }
        }
    }

    if (do_stats) {
#pragma unroll
        for (int i = 0; i < 16; i++) {
            float sv = csum[i], qv = csq[i];
            sv += __shfl_xor_sync(0xffffffffu, sv, 4);
            sv += __shfl_xor_sync(0xffffffffu, sv, 8);
            sv += __shfl_xor_sync(0xffffffffu, sv, 16);
            qv += __shfl_xor_sync(0xffffffffu, qv, 4);
            qv += __shfl_xor_sync(0xffffffffu, qv, 8);
            qv += __shfl_xor_sync(0xffffffffu, qv, 16);
            if (g == 0) {
                const int col = bcol + warp_n + (i >> 1) * 8 + t * 2 + (i & 1);
                red_add_f32(&stat[col], sv);
                red_add_f32(&stat[Nc + col], qv);
            }
        }
    }
}

// ---------------- BN ----------------
__global__ void zero_kernel(float* __restrict__ p, size_t n) {
    size_t idx = (size_t)blockIdx.x * blockDim.x + threadIdx.x;
    if (idx < n) p[idx] = 0.0f;
}

__global__ void bn_finalize_kernel(const float* __restrict__ stat,
                                   const float* __restrict__ gamma,
                                   const float* __restrict__ beta,
                                   float* __restrict__ ab) {
    int d = threadIdx.x;
    float mean = stat[d] * (1.0f / NN);
    float var = stat[DD + d] * (1.0f / NN) - mean * mean;
    float inv = rsqrtf(var + BN_EPS);
    float a = gamma[d] * inv;
    ab[d] = a;
    ab[DD + d] = beta[d] - mean * a;
}

__global__ void bn_apply_agg_kernel(float* __restrict__ h, const float* __restrict__ ab,
                                    const float* __restrict__ emb_next,
                                    float* __restrict__ agg, int act) {
    size_t idx = (size_t)blockIdx.x * blockDim.x + threadIdx.x;
    if (idx >= (size_t)NN * DD / 4) return;
    int d4 = (int)(idx & (DD / 4 - 1)) * 4;
    float4 v = *((float4*)h + idx);
    float4 a = *(const float4*)(ab + d4);
    float4 b = *(const float4*)(ab + DD + d4);
    v.x = v.x * a.x + b.x;
    v.y = v.y * a.y + b.y;
    v.z = v.z * a.z + b.z;
    v.w = v.w * a.w + b.w;
    if (act) {
        v.x = softplus_f(v.x);
        v.y = softplus_f(v.y);
        v.z = softplus_f(v.z);
        v.w = softplus_f(v.w);
    }
    *((float4*)h + idx) = v;
    if (agg) {
        float4 e = *(const float4*)(emb_next + d4);
        *((float4*)agg + idx) = make_float4(v.x + e.x, v.y + e.y, v.z + e.z, v.w + e.w);
    }
}

// ---------------- pooling ----------------
__global__ void pool_count_kernel(const int* __restrict__ batch, float* __restrict__ cnt) {
    int i = blockIdx.x * blockDim.x + threadIdx.x;
    if (i >= NN) return;
    atomicAdd(&cnt[batch[i]], 1.0f);
}

__global__ void pool_sum_kernel(const float* __restrict__ feat,
                                const int* __restrict__ batch,
                                float* __restrict__ ssum) {
    size_t idx = (size_t)blockIdx.x * blockDim.x + threadIdx.x;
    const int CH = FDIM / 4;
    const size_t nchunks = (NN + 7) / 8;
    if (idx >= nchunks * CH) return;
    int f4 = (int)(idx & (CH - 1)) * 4;
    int i0 = (int)(idx / CH) * 8;
    int cur = batch[i0];
    float4 acc = make_float4(0.f, 0.f, 0.f, 0.f);
#pragma unroll
    for (int r = 0; r < 8; r++) {
        int i = i0 + r;
        if (i >= NN) break;
        int b = batch[i];
        if (b != cur) {
            red_add_v4(&ssum[(size_t)cur * FDIM + f4], acc.x, acc.y, acc.z, acc.w);
            acc = make_float4(0.f, 0.f, 0.f, 0.f);
            cur = b;
        }
        float4 v = *(const float4*)(feat + (size_t)i * FDIM + f4);
        acc.x += v.x; acc.y += v.y; acc.z += v.z; acc.w += v.w;
    }
    red_add_v4(&ssum[(size_t)cur * FDIM + f4], acc.x, acc.y, acc.z, acc.w);
}

__global__ void gfeat_kernel(const float* __restrict__ ssum, const float* __restrict__ cnt,
                             float* __restrict__ gfeat) {
    size_t idx = (size_t)blockIdx.x * blockDim.x + threadIdx.x;
    if (idx >= (size_t)GG * FDIM) return;
    int g = (int)(idx / FDIM);
    gfeat[idx] = ssum[idx] / fmaxf(cnt[g], 1.0f);
}

__global__ void head_out_kernel(const float* __restrict__ hid, const float* __restrict__ w2,
                                const float* __restrict__ b2, float* __restrict__ out) {
    int g = blockIdx.x * (blockDim.x >> 5) + (threadIdx.x >> 5);
    if (g >= GG) return;
    int lane = threadIdx.x & 31;
    const float* hr = hid + (size_t)g * (FDIM / 2);
    float s = 0.f;
#pragma unroll
    for (int k = lane; k < FDIM / 2; k += 32) s += hr[k] * w2[k];
#pragma unroll
    for (int o = 16; o; o >>= 1) s += __shfl_down_sync(0xffffffffu, s, o);
    if (lane == 0) out[g] = s + b2[0];
}

// ---------------- host launch ----------------
static inline void launch_gemm(const float* A, const float* Bhi, const float* Blo,
                               const float* bias, float* C,
                               int M, int K, int Nc, int act, float* stat) {
    dim3 grid(Nc / 128, (M + 127) / 128);
    gemm_tf32<<<grid, 256, GEMM_SMEM_BYTES>>>(A, Bhi, Blo, bias, C, M, K, Nc, act, stat);
}

extern "C" void kernel_launch(void* const* d_in, const int* in_sizes, int n_in,
                              void* d_out, int out_size) {
    const int* atomics = (const int*)d_in[0];
    const float* pos = (const float*)d_in[1];
    const int* edge_index = (const int*)d_in[2];
    const int* edge_attr = (const int*)d_in[3];
    const int* batch = (const int*)d_in[4];
    const float* x_emb1 = (const float*)d_in[5];
    const float* x_emb2_w = (const float*)d_in[6];
    const float* x_emb2_b = (const float*)d_in[7];
    const float* edge_emb = (const float*)d_in[8];
    const float* mlp_w1 = (const float*)d_in[9];
    const float* mlp_b1 = (const float*)d_in[10];
    const float* mlp_w2 = (const float*)d_in[11];
    const float* mlp_b2 = (const float*)d_in[12];
    const float* bn_gamma = (const float*)d_in[13];
    const float* bn_beta = (const float*)d_in[14];
    const float* feat_w = (const float*)d_in[15];
    const float* feat_b = (const float*)d_in[16];
    const float* head_w1 = (const float*)d_in[17];
    const float* head_b1 = (const float*)d_in[18];
    const float* head_w2 = (const float*)d_in[19];
    const float* head_b2 = (const float*)d_in[20];
    float* out = (float*)d_out;

    float *h, *agg, *tmp, *stat, *ab, *ssum, *cnt, *gfeat, *hid, *whi, *wlo;
    cudaGetSymbolAddress((void**)&h, g_h);
    cudaGetSymbolAddress((void**)&agg, g_agg);
    cudaGetSymbolAddress((void**)&tmp, g_tmp);
    cudaGetSymbolAddress((void**)&stat, g_stat);
    cudaGetSymbolAddress((void**)&ab, g_ab);
    cudaGetSymbolAddress((void**)&ssum, g_ssum);
    cudaGetSymbolAddress((void**)&cnt, g_cnt);
    cudaGetSymbolAddress((void**)&gfeat, g_gfeat);
    cudaGetSymbolAddress((void**)&hid, g_hid);
    cudaGetSymbolAddress((void**)&whi, g_w_hi);
    cudaGetSymbolAddress((void**)&wlo, g_w_lo);

    cudaFuncSetAttribute(gemm_tf32, cudaFuncAttributeMaxDynamicSharedMemorySize,
                         GEMM_SMEM_BYTES);

    const size_t ND = (size_t)NN * DD;
    const size_t ND4 = ND / 4;
    const int EL = 256;

    // ---- weight prep: split hi/lo + permute columns per 128-tile ----
    split_perm_kernel<<<(655360 + EL - 1) / EL, EL>>>(mlp_w1, whi, wlo, 655360);
    split_perm_kernel<<<(655360 + EL - 1) / EL, EL>>>(mlp_w2, whi + 655360, wlo + 655360,
                                                      655360);
    split_perm_kernel<<<(131072 + EL - 1) / EL, EL>>>(feat_w, whi + 1310720, wlo + 1310720,
                                                      131072);
    split_perm_kernel<<<(131072 + EL - 1) / EL, EL>>>(head_w1, whi + 1441792, wlo + 1441792,
                                                      131072);

    init_h_kernel<<<(unsigned)((ND + EL - 1) / EL), EL>>>(atomics, pos, x_emb1, x_emb2_w,
                                                          x_emb2_b, h);
    {
        const float* emb_self0 =
            edge_emb + (size_t)0 * NUM_BOND_C * DD + (size_t)(NUM_BOND_C - 1) * DD;
        agg_init_kernel<<<(unsigned)((ND4 + EL - 1) / EL), EL>>>(h, emb_self0, agg);
    }

    for (int l = 0; l < LL; l++) {
        const float* emb_l = edge_emb + (size_t)l * NUM_BOND_C * DD;

        scatter_edges_kernel<<<(EE + 7) / 8, 256>>>(h, edge_index, edge_attr, emb_l, agg);

        // tmp = softplus(agg @ W1 + b1)   [N, 512]
        launch_gemm(agg, whi + (size_t)l * 131072, wlo + (size_t)l * 131072,
                    mlp_b1 + (size_t)l * 2 * DD, tmp, NN, DD, 2 * DD, 1, nullptr);

        zero_kernel<<<1, 512>>>(stat, 2 * DD);
        // h = tmp @ W2 + b2  (+ BN stats)   [N, 256]
        launch_gemm(tmp, whi + 655360 + (size_t)l * 131072, wlo + 655360 + (size_t)l * 131072,
                    mlp_b2 + (size_t)l * DD, h, NN, 2 * DD, DD, 0, stat);

        bn_finalize_kernel<<<1, 256>>>(stat, bn_gamma + (size_t)l * DD,
                                       bn_beta + (size_t)l * DD, ab);

        if (l < LL - 1) {
            const float* emb_self_next =
                edge_emb + (size_t)(l + 1) * NUM_BOND_C * DD + (size_t)(NUM_BOND_C - 1) * DD;
            bn_apply_agg_kernel<<<(unsigned)((ND4 + EL - 1) / EL), EL>>>(h, ab, emb_self_next,
                                                                         agg, 1);
        } else {
            bn_apply_agg_kernel<<<(unsigned)((ND4 + EL - 1) / EL), EL>>>(h, ab, nullptr,
                                                                         nullptr, 0);
        }
    }

    // feat = h @ feat_w + feat_b
    launch_gemm(h, whi + 1310720, wlo + 1310720, feat_b, tmp, NN, DD, FDIM, 0, nullptr);

    // global mean pool
    zero_kernel<<<(unsigned)(((size_t)GG * FDIM + EL - 1) / EL), EL>>>(ssum, (size_t)GG * FDIM);
    zero_kernel<<<(GG + EL - 1) / EL, EL>>>(cnt, GG);
    pool_count_kernel<<<(NN + EL - 1) / EL, EL>>>(batch, cnt);
    {
        size_t total = ((NN + 7) / 8) * (size_t)(FDIM / 4);
        pool_sum_kernel<<<(unsigned)((total + EL - 1) / EL), EL>>>(tmp, batch, ssum);
    }
    gfeat_kernel<<<(unsigned)(((size_t)GG * FDIM + EL - 1) / EL), EL>>>(ssum, cnt, gfeat);

    // hid = softplus(gfeat @ head_w1 + head_b1)
    launch_gemm(gfeat, whi + 1441792, wlo + 1441792, head_b1, hid, GG, FDIM, FDIM / 2, 1,
                nullptr);
    head_out_kernel<<<(GG + 7) / 8, 256>>>(hid, head_w2, head_b2, out);
}

// round 7
// speedup vs baseline: 1.7996x; 1.7996x over previous
#include <cuda_runtime.h>
#include <cuda_fp16.h>
#include <math.h>
#include <stdint.h>

#define NN 100000
#define EE 300000
#define DD 256
#define FDIM 512
#define LL 5
#define GG 4000
#define NUM_BOND_C 2
#define BN_EPS 1e-5f
#define MPAD_N 100096   // 782*128
#define MPAD_G 4096     // 32*128

// ---------------- scratch (device globals: no allocation allowed) ----------------
__device__ float g_h[(size_t)NN * DD];
__device__ float g_agg[(size_t)NN * DD];
__device__ float g_tmp[(size_t)NN * FDIM];
__device__ float g_stat[2 * FDIM];
__device__ float g_ab[2 * DD];
__device__ float g_ssum[(size_t)GG * FDIM];
__device__ float g_cnt[GG];
__device__ float g_gfeat[(size_t)GG * FDIM];
__device__ float g_hid[(size_t)GG * (FDIM / 2)];
// fp16 hi/lo fragment-format buffers
// A16 chunk = (16 rows x 16 k): 64 uint4 = [plane2][lane32][reg4 u32]
__device__ uint4 g_a16a[(size_t)(MPAD_N / 16) * (DD / 16) * 64];      // K=256 operand
__device__ uint4 g_a16b[(size_t)(MPAD_N / 16) * (FDIM / 16) * 64];    // K=512 operand
// B16 chunk = (8 cols x 16 k): 32 uint4 = [lane32][hi0,hi1,lo0,lo1]
// offsets (uint4): w1[l]@l*32768 | w2[l]@163840+l*32768 | feat@327680 | head@360448
__device__ uint4 g_w16[393216];

__device__ __forceinline__ float softplus_f(float x) {
    return fmaxf(x, 0.0f) + log1pf(expf(-fabsf(x)));
}

__device__ __forceinline__ void red_add_v4(float* p, float x, float y, float z, float w) {
    asm volatile("red.global.add.v4.f32 [%0], {%1,%2,%3,%4};"
                 :: "l"(p), "f"(x), "f"(y), "f"(z), "f"(w) : "memory");
}
__device__ __forceinline__ void red_add_f32(float* p, float v) {
    asm volatile("red.global.add.f32 [%0], %1;" :: "l"(p), "f"(v) : "memory");
}

// ---------------- fp16 split helpers ----------------
__device__ __forceinline__ void packhl(float x, float y, uint32_t& hi, uint32_t& lo) {
    __half2 h = __floats2half2_rn(x, y);             // low half = x
    float2 hf = __half22float2(h);
    __half2 l = __floats2half2_rn(x - hf.x, y - hf.y);
    hi = *reinterpret_cast<uint32_t*>(&h);
    lo = *reinterpret_cast<uint32_t*>(&l);
}

__device__ __forceinline__ void mma16(float* c, const uint32_t* a, uint32_t b0, uint32_t b1) {
    asm volatile(
        "mma.sync.aligned.m16n8k16.row.col.f32.f16.f16.f32 "
        "{%0,%1,%2,%3},{%4,%5,%6,%7},{%8,%9},{%0,%1,%2,%3};"
        : "+f"(c[0]), "+f"(c[1]), "+f"(c[2]), "+f"(c[3])
        : "r"(a[0]), "r"(a[1]), "r"(a[2]), "r"(a[3]), "r"(b0), "r"(b1));
}

__device__ __forceinline__ void cpa16f(void* dst, const void* src) {
    uint32_t d = (uint32_t)__cvta_generic_to_shared(dst);
    asm volatile("cp.async.cg.shared.global [%0], [%1], 16;" :: "r"(d), "l"(src) : "memory");
}
__device__ __forceinline__ void cp_commit() {
    asm volatile("cp.async.commit_group;" ::: "memory");
}
__device__ __forceinline__ void cp_wait0() {
    asm volatile("cp.async.wait_group 0;" ::: "memory");
}

// ---------------- converters to fragment format ----------------
// A16: one warp per (16-row, 16-k) chunk
__global__ void conv_a16(const float* __restrict__ src, uint4* __restrict__ dst,
                         int M, int Mpad, int K) {
    int Q = K >> 4;
    int wid = blockIdx.x * (blockDim.x >> 5) + (threadIdx.x >> 5);
    int nch = (Mpad >> 4) * Q;
    if (wid >= nch) return;
    int bm = wid / Q, q = wid - bm * Q;
    int lane = threadIdx.x & 31, g = lane >> 2, t = lane & 3;
    int r0 = bm * 16 + g, r1 = r0 + 8;
    int k0 = q * 16 + 2 * t, k1 = k0 + 8;
    float2 z = make_float2(0.f, 0.f);
    float2 f00 = (r0 < M) ? *(const float2*)(src + (size_t)r0 * K + k0) : z;
    float2 f10 = (r1 < M) ? *(const float2*)(src + (size_t)r1 * K + k0) : z;
    float2 f01 = (r0 < M) ? *(const float2*)(src + (size_t)r0 * K + k1) : z;
    float2 f11 = (r1 < M) ? *(const float2*)(src + (size_t)r1 * K + k1) : z;
    uint4 hi, lo;
    packhl(f00.x, f00.y, hi.x, lo.x);
    packhl(f10.x, f10.y, hi.y, lo.y);
    packhl(f01.x, f01.y, hi.z, lo.z);
    packhl(f11.x, f11.y, hi.w, lo.w);
    dst[(size_t)wid * 64 + lane] = hi;
    dst[(size_t)wid * 64 + 32 + lane] = lo;
}

// B16: one warp per (8-col, 16-k) chunk; W is [K,N] row-major
__global__ void conv_b16(const float* __restrict__ W, uint4* __restrict__ dst, int K, int N) {
    int Q = K >> 4;
    int wid = blockIdx.x * (blockDim.x >> 5) + (threadIdx.x >> 5);
    int nch = (N >> 3) * Q;
    if (wid >= nch) return;
    int bn = wid / Q, q = wid - bn * Q;
    int lane = threadIdx.x & 31, g = lane >> 2, t = lane & 3;
    int n = bn * 8 + g;
    int k0 = q * 16 + 2 * t, k1 = k0 + 8;
    uint4 v;
    uint32_t l0, l1;
    packhl(W[(size_t)k0 * N + n], W[(size_t)(k0 + 1) * N + n], v.x, l0);
    packhl(W[(size_t)k1 * N + n], W[(size_t)(k1 + 1) * N + n], v.y, l1);
    v.z = l0;
    v.w = l1;
    dst[(size_t)wid * 32 + lane] = v;
}

// ---------------- fp16x3 tensor-core GEMM ----------------
// A16 fragment-format [Mpad, K], B16 fragment-format [Nc, K].
// 128x128 CTA tile, BK=32 (2 k16-steps/stage), 2-stage cp.async, 8 warps (4x2).
// outputs: C fp32 (opt), O16 fragment-format (opt), BN stats (opt).
// smem/stage (uint4): A 16 chunks*64 = 1024 | B 32 chunks*32 = 1024; 2 stages = 4096 u4 = 64KB
#define GEMM_SMEM_BYTES 65536

__global__ __launch_bounds__(256, 2)
void gemm_f16(const uint4* __restrict__ A16, const uint4* __restrict__ B16,
              const float* __restrict__ bias, float* __restrict__ C,
              uint4* __restrict__ O16, int M, int Qa, int Nc, int act,
              float* __restrict__ stat, int Qout) {
    extern __shared__ uint4 sm4[];
    const int tid = threadIdx.x, lane = tid & 31, w = tid >> 5;
    const int g = lane >> 2, t = lane & 3;
    const int wm = (w >> 1) * 32, wn = (w & 1) * 64;
    const int brow = blockIdx.y * 128, bcol = blockIdx.x * 128;

    // fill descriptors (4 A + 4 B cpa16 per thread per stage)
    const uint4* asrc[4];
    uint4* adst[4];
    const uint4* bsrc[4];
    uint4* bdst[4];
#pragma unroll
    for (int j = 0; j < 4; j++) {
        int u = tid + j * 256;
        {
            int chunk = u >> 6, wd = u & 63;
            int bm = chunk >> 1, ql = chunk & 1;
            asrc[j] = A16 + ((size_t)((brow >> 4) + bm) * Qa + ql) * 64 + wd;
            adst[j] = sm4 + (ql * 8 + bm) * 64 + wd;
        }
        {
            int chunk = u >> 5, wd = u & 31;
            int bn = chunk >> 1, ql = chunk & 1;
            bsrc[j] = B16 + ((size_t)((bcol >> 3) + bn) * Qa + ql) * 32 + wd;
            bdst[j] = sm4 + 1024 + (ql * 16 + bn) * 32 + wd;
        }
    }

    float acc[2][8][4];
#pragma unroll
    for (int mt = 0; mt < 2; mt++)
#pragma unroll
        for (int nt = 0; nt < 8; nt++)
#pragma unroll
            for (int q = 0; q < 4; q++) acc[mt][nt][q] = 0.0f;

    const int S = Qa >> 1;

#pragma unroll
    for (int j = 0; j < 4; j++) {
        cpa16f(adst[j], asrc[j]);
        cpa16f(bdst[j], bsrc[j]);
    }
    cp_commit();

    for (int s = 0; s < S; s++) {
        const int st = s & 1;
        cp_wait0();
        __syncthreads();
        if (s + 1 < S) {
            const int st2 = st ^ 1;
#pragma unroll
            for (int j = 0; j < 4; j++) {
                cpa16f(adst[j] + st2 * 2048, asrc[j] + (size_t)(s + 1) * 128);
                cpa16f(bdst[j] + st2 * 2048, bsrc[j] + (size_t)(s + 1) * 64);
            }
        }
        cp_commit();

#pragma unroll
        for (int ql = 0; ql < 2; ql++) {
            uint4 ah[2], al[2];
#pragma unroll
            for (int mt = 0; mt < 2; mt++) {
                const uint4* ap = sm4 + st * 2048 + (ql * 8 + (wm >> 4) + mt) * 64;
                ah[mt] = ap[lane];
                al[mt] = ap[32 + lane];
            }
#pragma unroll
            for (int nt = 0; nt < 8; nt++) {
                uint4 bv = sm4[st * 2048 + 1024 + (ql * 16 + (wn >> 3) + nt) * 32 + lane];
#pragma unroll
                for (int mt = 0; mt < 2; mt++) {
                    mma16(acc[mt][nt], (const uint32_t*)&ah[mt], bv.x, bv.y);
                    mma16(acc[mt][nt], (const uint32_t*)&ah[mt], bv.z, bv.w);
                    mma16(acc[mt][nt], (const uint32_t*)&al[mt], bv.x, bv.y);
                }
            }
        }
    }

    // ---------------- epilogue ----------------
    const bool do_stats = (stat != nullptr);
    float csum[16], csq[16];
    if (do_stats) {
#pragma unroll
        for (int i = 0; i < 16; i++) { csum[i] = 0.f; csq[i] = 0.f; }
    }

#pragma unroll
    for (int mt = 0; mt < 2; mt++) {
        const int r0 = brow + wm + mt * 16 + g;
        const int r1 = r0 + 8;
#pragma unroll
        for (int j = 0; j < 4; j++) {
            float v[2][4];
#pragma unroll
            for (int e = 0; e < 2; e++) {
                const int nt = j * 2 + e;
                const int col = bcol + wn + nt * 8 + t * 2;
                const float b0 = bias[col];
                const float b1 = bias[col + 1];
                float x0 = acc[mt][nt][0] + b0;
                float x1 = acc[mt][nt][1] + b1;
                float x2 = acc[mt][nt][2] + b0;
                float x3 = acc[mt][nt][3] + b1;
                if (act) {
                    x0 = softplus_f(x0); x1 = softplus_f(x1);
                    x2 = softplus_f(x2); x3 = softplus_f(x3);
                }
                if (r0 >= M) { x0 = 0.f; x1 = 0.f; }
                if (r1 >= M) { x2 = 0.f; x3 = 0.f; }
                v[e][0] = x0; v[e][1] = x1; v[e][2] = x2; v[e][3] = x3;
                if (C) {
                    if (r0 < M) *(float2*)&C[(size_t)r0 * Nc + col] = make_float2(x0, x1);
                    if (r1 < M) *(float2*)&C[(size_t)r1 * Nc + col] = make_float2(x2, x3);
                }
                if (do_stats) {
                    csum[nt * 2] += x0 + x2;
                    csq[nt * 2] += x0 * x0 + x2 * x2;
                    csum[nt * 2 + 1] += x1 + x3;
                    csq[nt * 2 + 1] += x1 * x1 + x3 * x3;
                }
            }
            if (O16) {
                uint4 hi, lo;
                packhl(v[0][0], v[0][1], hi.x, lo.x);
                packhl(v[0][2], v[0][3], hi.y, lo.y);
                packhl(v[1][0], v[1][1], hi.z, lo.z);
                packhl(v[1][2], v[1][3], hi.w, lo.w);
                size_t chunk = (size_t)((brow + wm + mt * 16) >> 4) * Qout +
                               ((bcol + wn) >> 4) + j;
                O16[chunk * 64 + lane] = hi;
                O16[chunk * 64 + 32 + lane] = lo;
            }
        }
    }

    if (do_stats) {
#pragma unroll
        for (int i = 0; i < 16; i++) {
            float sv = csum[i], qv = csq[i];
            sv += __shfl_xor_sync(0xffffffffu, sv, 4);
            sv += __shfl_xor_sync(0xffffffffu, sv, 8);
            sv += __shfl_xor_sync(0xffffffffu, sv, 16);
            qv += __shfl_xor_sync(0xffffffffu, qv, 4);
            qv += __shfl_xor_sync(0xffffffffu, qv, 8);
            qv += __shfl_xor_sync(0xffffffffu, qv, 16);
            if (g == 0) {
                const int col = bcol + wn + (i >> 1) * 8 + t * 2 + (i & 1);
                red_add_f32(&stat[col], sv);
                red_add_f32(&stat[Nc + col], qv);
            }
        }
    }
}

// ---------------- non-GEMM kernels (unchanged from R3 best) ----------------
__global__ void init_h_kernel(const int* __restrict__ atomics,
                              const float* __restrict__ pos,
                              const float* __restrict__ emb1,
                              const float* __restrict__ w2,
                              const float* __restrict__ b2,
                              float* __restrict__ h) {
    size_t idx = (size_t)blockIdx.x * blockDim.x + threadIdx.x;
    if (idx >= (size_t)NN * DD) return;
    int i = (int)(idx / DD);
    int d = (int)(idx & (DD - 1));
    float p0 = pos[i * 3 + 0], p1 = pos[i * 3 + 1], p2 = pos[i * 3 + 2];
    float v = emb1[(size_t)atomics[i] * DD + d];
    v += p0 * w2[d] + p1 * w2[DD + d] + p2 * w2[2 * DD + d] + b2[d];
    h[idx] = v;
}

__global__ void agg_init_kernel(const float* __restrict__ h,
                                const float* __restrict__ emb_self,
                                float* __restrict__ agg) {
    size_t idx = (size_t)blockIdx.x * blockDim.x + threadIdx.x;
    if (idx >= (size_t)NN * DD / 4) return;
    int d4 = (int)(idx & (DD / 4 - 1)) * 4;
    float4 hv = *((const float4*)h + idx);
    float4 ev = *(const float4*)(emb_self + d4);
    *((float4*)agg + idx) = make_float4(hv.x + ev.x, hv.y + ev.y, hv.z + ev.z, hv.w + ev.w);
}

__global__ void scatter_edges_kernel(const float* __restrict__ h,
                                     const int* __restrict__ edge_index,
                                     const int* __restrict__ edge_attr,
                                     const float* __restrict__ emb,
                                     float* __restrict__ agg) {
    int e = blockIdx.x * (blockDim.x >> 5) + (threadIdx.x >> 5);
    if (e >= EE) return;
    int lane = threadIdx.x & 31;
    int s = edge_index[e];
    int t = edge_index[EE + e];
    const float* hs = h + (size_t)s * DD;
    const float* eb = emb + (size_t)edge_attr[e] * DD;
    float* ag = agg + (size_t)t * DD;
#pragma unroll
    for (int half = 0; half < 2; half++) {
        int c = lane * 4 + half * 128;
        float4 hv = *(const float4*)(hs + c);
        float4 ev = *(const float4*)(eb + c);
        red_add_v4(ag + c, hv.x + ev.x, hv.y + ev.y, hv.z + ev.z, hv.w + ev.w);
    }
}

__global__ void zero_kernel(float* __restrict__ p, size_t n) {
    size_t idx = (size_t)blockIdx.x * blockDim.x + threadIdx.x;
    if (idx < n) p[idx] = 0.0f;
}

__global__ void bn_finalize_kernel(const float* __restrict__ stat,
                                   const float* __restrict__ gamma,
                                   const float* __restrict__ beta,
                                   float* __restrict__ ab) {
    int d = threadIdx.x;
    float mean = stat[d] * (1.0f / NN);
    float var = stat[DD + d] * (1.0f / NN) - mean * mean;
    float inv = rsqrtf(var + BN_EPS);
    float a = gamma[d] * inv;
    ab[d] = a;
    ab[DD + d] = beta[d] - mean * a;
}

__global__ void bn_apply_agg_kernel(float* __restrict__ h, const float* __restrict__ ab,
                                    const float* __restrict__ emb_next,
                                    float* __restrict__ agg, int act) {
    size_t idx = (size_t)blockIdx.x * blockDim.x + threadIdx.x;
    if (idx >= (size_t)NN * DD / 4) return;
    int d4 = (int)(idx & (DD / 4 - 1)) * 4;
    float4 v = *((float4*)h + idx);
    float4 a = *(const float4*)(ab + d4);
    float4 b = *(const float4*)(ab + DD + d4);
    v.x = v.x * a.x + b.x;
    v.y = v.y * a.y + b.y;
    v.z = v.z * a.z + b.z;
    v.w = v.w * a.w + b.w;
    if (act) {
        v.x = softplus_f(v.x);
        v.y = softplus_f(v.y);
        v.z = softplus_f(v.z);
        v.w = softplus_f(v.w);
    }
    *((float4*)h + idx) = v;
    if (agg) {
        float4 e = *(const float4*)(emb_next + d4);
        *((float4*)agg + idx) = make_float4(v.x + e.x, v.y + e.y, v.z + e.z, v.w + e.w);
    }
}

__global__ void pool_count_kernel(const int* __restrict__ batch, float* __restrict__ cnt) {
    int i = blockIdx.x * blockDim.x + threadIdx.x;
    if (i >= NN) return;
    atomicAdd(&cnt[batch[i]], 1.0f);
}

__global__ void pool_sum_kernel(const float* __restrict__ feat,
                                const int* __restrict__ batch,
                                float* __restrict__ ssum) {
    size_t idx = (size_t)blockIdx.x * blockDim.x + threadIdx.x;
    const int CH = FDIM / 4;
    const size_t nchunks = (NN + 7) / 8;
    if (idx >= nchunks * CH) return;
    int f4 = (int)(idx & (CH - 1)) * 4;
    int i0 = (int)(idx / CH) * 8;
    int cur = batch[i0];
    float4 acc = make_float4(0.f, 0.f, 0.f, 0.f);
#pragma unroll
    for (int r = 0; r < 8; r++) {
        int i = i0 + r;
        if (i >= NN) break;
        int b = batch[i];
        if (b != cur) {
            red_add_v4(&ssum[(size_t)cur * FDIM + f4], acc.x, acc.y, acc.z, acc.w);
            acc = make_float4(0.f, 0.f, 0.f, 0.f);
            cur = b;
        }
        float4 v = *(const float4*)(feat + (size_t)i * FDIM + f4);
        acc.x += v.x; acc.y += v.y; acc.z += v.z; acc.w += v.w;
    }
    red_add_v4(&ssum[(size_t)cur * FDIM + f4], acc.x, acc.y, acc.z, acc.w);
}

__global__ void gfeat_kernel(const float* __restrict__ ssum, const float* __restrict__ cnt,
                             float* __restrict__ gfeat) {
    size_t idx = (size_t)blockIdx.x * blockDim.x + threadIdx.x;
    if (idx >= (size_t)GG * FDIM) return;
    int g = (int)(idx / FDIM);
    gfeat[idx] = ssum[idx] / fmaxf(cnt[g], 1.0f);
}

__global__ void head_out_kernel(const float* __restrict__ hid, const float* __restrict__ w2,
                                const float* __restrict__ b2, float* __restrict__ out) {
    int g = blockIdx.x * (blockDim.x >> 5) + (threadIdx.x >> 5);
    if (g >= GG) return;
    int lane = threadIdx.x & 31;
    const float* hr = hid + (size_t)g * (FDIM / 2);
    float s = 0.f;
#pragma unroll
    for (int k = lane; k < FDIM / 2; k += 32) s += hr[k] * w2[k];
#pragma unroll
    for (int o = 16; o; o >>= 1) s += __shfl_down_sync(0xffffffffu, s, o);
    if (lane == 0) out[g] = s + b2[0];
}

// ---------------- host launch ----------------
static inline void launch_gemm(const uint4* A16, const uint4* B16, const float* bias,
                               float* C, uint4* O16, int M, int Mpad, int Qa, int Nc,
                               int act, float* stat, int Qout) {
    dim3 grid(Nc / 128, Mpad / 128);
    gemm_f16<<<grid, 256, GEMM_SMEM_BYTES>>>(A16, B16, bias, C, O16, M, Qa, Nc, act, stat,
                                             Qout);
}

extern "C" void kernel_launch(void* const* d_in, const int* in_sizes, int n_in,
                              void* d_out, int out_size) {
    const int* atomics = (const int*)d_in[0];
    const float* pos = (const float*)d_in[1];
    const int* edge_index = (const int*)d_in[2];
    const int* edge_attr = (const int*)d_in[3];
    const int* batch = (const int*)d_in[4];
    const float* x_emb1 = (const float*)d_in[5];
    const float* x_emb2_w = (const float*)d_in[6];
    const float* x_emb2_b = (const float*)d_in[7];
    const float* edge_emb = (const float*)d_in[8];
    const float* mlp_w1 = (const float*)d_in[9];
    const float* mlp_b1 = (const float*)d_in[10];
    const float* mlp_w2 = (const float*)d_in[11];
    const float* mlp_b2 = (const float*)d_in[12];
    const float* bn_gamma = (const float*)d_in[13];
    const float* bn_beta = (const float*)d_in[14];
    const float* feat_w = (const float*)d_in[15];
    const float* feat_b = (const float*)d_in[16];
    const float* head_w1 = (const float*)d_in[17];
    const float* head_b1 = (const float*)d_in[18];
    const float* head_w2 = (const float*)d_in[19];
    const float* head_b2 = (const float*)d_in[20];
    float* out = (float*)d_out;

    float *h, *agg, *tmp, *stat, *ab, *ssum, *cnt, *gfeat, *hid;
    uint4 *a16a, *a16b, *w16;
    cudaGetSymbolAddress((void**)&h, g_h);
    cudaGetSymbolAddress((void**)&agg, g_agg);
    cudaGetSymbolAddress((void**)&tmp, g_tmp);
    cudaGetSymbolAddress((void**)&stat, g_stat);
    cudaGetSymbolAddress((void**)&ab, g_ab);
    cudaGetSymbolAddress((void**)&ssum, g_ssum);
    cudaGetSymbolAddress((void**)&cnt, g_cnt);
    cudaGetSymbolAddress((void**)&gfeat, g_gfeat);
    cudaGetSymbolAddress((void**)&hid, g_hid);
    cudaGetSymbolAddress((void**)&a16a, g_a16a);
    cudaGetSymbolAddress((void**)&a16b, g_a16b);
    cudaGetSymbolAddress((void**)&w16, g_w16);

    cudaFuncSetAttribute(gemm_f16, cudaFuncAttributeMaxDynamicSharedMemorySize,
                         GEMM_SMEM_BYTES);

    const size_t ND = (size_t)NN * DD;
    const size_t ND4 = ND / 4;
    const int EL = 256;

    // ---- B16 prep: each weight -> fragment-format fp16 hi/lo ----
    // chunks: W1 (256x512): 64*16=1024; W2 (512x256): 32*32=1024; feat 1024; head 1024
    for (int l = 0; l < LL; l++) {
        conv_b16<<<128, 256>>>(mlp_w1 + (size_t)l * DD * 2 * DD, w16 + l * 32768, DD, 2 * DD);
        conv_b16<<<128, 256>>>(mlp_w2 + (size_t)l * 2 * DD * DD, w16 + 163840 + l * 32768,
                               2 * DD, DD);
    }
    conv_b16<<<128, 256>>>(feat_w, w16 + 327680, DD, FDIM);
    conv_b16<<<128, 256>>>(head_w1, w16 + 360448, FDIM, FDIM / 2);

    init_h_kernel<<<(unsigned)((ND + EL - 1) / EL), EL>>>(atomics, pos, x_emb1, x_emb2_w,
                                                          x_emb2_b, h);
    {
        const float* emb_self0 =
            edge_emb + (size_t)0 * NUM_BOND_C * DD + (size_t)(NUM_BOND_C - 1) * DD;
        agg_init_kernel<<<(unsigned)((ND4 + EL - 1) / EL), EL>>>(h, emb_self0, agg);
    }

    const int NCHUNK_A = (MPAD_N / 16) * (DD / 16);  // 100096 warps

    for (int l = 0; l < LL; l++) {
        const float* emb_l = edge_emb + (size_t)l * NUM_BOND_C * DD;

        scatter_edges_kernel<<<(EE + 7) / 8, 256>>>(h, edge_index, edge_attr, emb_l, agg);

        // agg -> fragment fp16
        conv_a16<<<(NCHUNK_A + 7) / 8, 256>>>(agg, a16a, NN, MPAD_N, DD);

        // tmp16 = softplus(agg @ W1 + b1)  [N,512] (fragment format only)
        launch_gemm(a16a, w16 + l * 32768, mlp_b1 + (size_t)l * 2 * DD, nullptr, a16b,
                    NN, MPAD_N, DD / 16, 2 * DD, 1, nullptr, FDIM / 16);

        zero_kernel<<<1, 512>>>(stat, 2 * DD);
        // h = tmp16 @ W2 + b2 (+BN stats)  [N,256] fp32
        launch_gemm(a16b, w16 + 163840 + l * 32768, mlp_b2 + (size_t)l * DD, h, nullptr,
                    NN, MPAD_N, FDIM / 16, DD, 0, stat, 1);

        bn_finalize_kernel<<<1, 256>>>(stat, bn_gamma + (size_t)l * DD,
                                       bn_beta + (size_t)l * DD, ab);

        if (l < LL - 1) {
            const float* emb_self_next =
                edge_emb + (size_t)(l + 1) * NUM_BOND_C * DD + (size_t)(NUM_BOND_C - 1) * DD;
            bn_apply_agg_kernel<<<(unsigned)((ND4 + EL - 1) / EL), EL>>>(h, ab, emb_self_next,
                                                                         agg, 1);
        } else {
            bn_apply_agg_kernel<<<(unsigned)((ND4 + EL - 1) / EL), EL>>>(h, ab, nullptr,
                                                                         nullptr, 0);
        }
    }

    // feat = h @ feat_w + feat_b -> tmp fp32
    conv_a16<<<(NCHUNK_A + 7) / 8, 256>>>(h, a16a, NN, MPAD_N, DD);
    launch_gemm(a16a, w16 + 327680, feat_b, tmp, nullptr, NN, MPAD_N, DD / 16, FDIM, 0,
                nullptr, 1);

    // global mean pool
    zero_kernel<<<(unsigned)(((size_t)GG * FDIM + EL - 1) / EL), EL>>>(ssum, (size_t)GG * FDIM);
    zero_kernel<<<(GG + EL - 1) / EL, EL>>>(cnt, GG);
    pool_count_kernel<<<(NN + EL - 1) / EL, EL>>>(batch, cnt);
    {
        size_t total = ((NN + 7) / 8) * (size_t)(FDIM / 4);
        pool_sum_kernel<<<(unsigned)((total + EL - 1) / EL), EL>>>(tmp, batch, ssum);
    }
    gfeat_kernel<<<(unsigned)(((size_t)GG * FDIM + EL - 1) / EL), EL>>>(ssum, cnt, gfeat);

    // head: hid = softplus(gfeat @ head_w1 + head_b1)
    {
        const int nch_g = (MPAD_G / 16) * (FDIM / 16);  // 8192
        conv_a16<<<(nch_g + 7) / 8, 256>>>(gfeat, a16b, GG, MPAD_G, FDIM);
        launch_gemm(a16b, w16 + 360448, head_b1, hid, nullptr, GG, MPAD_G, FDIM / 16,
                    FDIM / 2, 1, nullptr, 1);
    }
    head_out_kernel<<<(GG + 7) / 8, 256>>>(hid, head_w2, head_b2, out);
}